// round 4
// baseline (speedup 1.0000x reference)
#include <cuda_runtime.h>
#include <math.h>

#define NN 100000
#define NE 1600000
#define SCAN_CHUNK 1024
#define NCHUNK ((NN + SCAN_CHUNK - 1) / SCAN_CHUNK)   // 98

// ---------------- scratch (allocation-free) ----------------
__device__ __align__(16) float g_y[NN * 16];   // W_l-projected features
__device__ __align__(16) float g_z[NN * 16];   // W_r-projected + bias
__device__ __align__(16) float g_h[NN * 16];   // layer output
__device__ int g_cnt[NN];                      // in-degree histogram
__device__ int g_off[NN + 1];                  // CSR row offsets
__device__ int g_cur[NN];                      // placement cursors
__device__ int g_csr[NE];                      // CSR src indices (grouped by dst)
__device__ int g_part[NCHUNK];                 // scan partials

__device__ __forceinline__ float elu_f(float v) {
    return v > 0.0f ? v : expm1f(v);
}

// ---------------------------------------------------------------------------
// CSR build: memset -> histogram -> 3-step scan -> place
// ---------------------------------------------------------------------------
__global__ void hist_kernel(const int* __restrict__ dst, int* __restrict__ cnt) {
    int e = blockIdx.x * blockDim.x + threadIdx.x;
    if (e < NE) atomicAdd(cnt + __ldg(dst + e), 1);   // RED (no return)
}

__global__ void scan1_kernel(const int* __restrict__ cnt, int* __restrict__ part) {
    __shared__ int red[256];
    int b = blockIdx.x;
    int sum = 0;
    for (int i = threadIdx.x; i < SCAN_CHUNK; i += 256) {
        int idx = b * SCAN_CHUNK + i;
        if (idx < NN) sum += cnt[idx];
    }
    red[threadIdx.x] = sum;
    __syncthreads();
    for (int s = 128; s > 0; s >>= 1) {
        if (threadIdx.x < s) red[threadIdx.x] += red[threadIdx.x + s];
        __syncthreads();
    }
    if (threadIdx.x == 0) part[b] = red[0];
}

// Parallel exclusive scan of NCHUNK(=98) partials: 1 warp, 4 elems/lane.
__global__ void scan2_kernel(int* __restrict__ part) {
    int lane = threadIdx.x;
    int base = lane * 4;
    int v[4];
#pragma unroll
    for (int k = 0; k < 4; k++)
        v[k] = (base + k < NCHUNK) ? part[base + k] : 0;
    int s = v[0] + v[1] + v[2] + v[3];
    int sc = s;
#pragma unroll
    for (int o = 1; o < 32; o <<= 1) {
        int n = __shfl_up_sync(0xffffffff, sc, o);
        if (lane >= o) sc += n;
    }
    int excl = sc - s;
#pragma unroll
    for (int k = 0; k < 4; k++) {
        if (base + k < NCHUNK) part[base + k] = excl;
        excl += v[k];
    }
}

__global__ void scan3_kernel(const int* __restrict__ cnt, const int* __restrict__ part,
                             int* __restrict__ off, int* __restrict__ cur) {
    __shared__ int wsum[8];
    int b = blockIdx.x, t = threadIdx.x;
    int gbase = b * SCAN_CHUNK + t * 4;
    int v0 = (gbase + 0 < NN) ? cnt[gbase + 0] : 0;
    int v1 = (gbase + 1 < NN) ? cnt[gbase + 1] : 0;
    int v2 = (gbase + 2 < NN) ? cnt[gbase + 2] : 0;
    int v3 = (gbase + 3 < NN) ? cnt[gbase + 3] : 0;
    int s = v0 + v1 + v2 + v3;

    int lane = t & 31, wid = t >> 5;
    int sc = s;
#pragma unroll
    for (int o = 1; o < 32; o <<= 1) {
        int n = __shfl_up_sync(0xffffffff, sc, o);
        if (lane >= o) sc += n;
    }
    if (lane == 31) wsum[wid] = sc;
    __syncthreads();
    if (wid == 0) {
        int ws = (lane < 8) ? wsum[lane] : 0;
#pragma unroll
        for (int o = 1; o < 8; o <<= 1) {
            int n = __shfl_up_sync(0xffffffff, ws, o);
            if (lane >= o) ws += n;
        }
        if (lane < 8) wsum[lane] = ws;   // inclusive warp sums
    }
    __syncthreads();

    int excl = sc - s + (wid > 0 ? wsum[wid - 1] : 0) + part[b];
    if (gbase + 0 < NN) { off[gbase + 0] = excl; cur[gbase + 0] = excl; } excl += v0;
    if (gbase + 1 < NN) { off[gbase + 1] = excl; cur[gbase + 1] = excl; } excl += v1;
    if (gbase + 2 < NN) { off[gbase + 2] = excl; cur[gbase + 2] = excl; } excl += v2;
    if (gbase + 3 < NN) { off[gbase + 3] = excl; cur[gbase + 3] = excl; }
    if (b == 0 && t == 0) off[NN] = NE;
}

__global__ void place_kernel(const int* __restrict__ src, const int* __restrict__ dst,
                             int* __restrict__ cur, int* __restrict__ csr) {
    int e = blockIdx.x * blockDim.x + threadIdx.x;
    if (e >= NE) return;
    int d = __ldg(dst + e);
    int p = atomicAdd(cur + d, 1);
    csr[p] = __ldg(src + e);
}

// ---------------------------------------------------------------------------
// Transform: gridDim.y selects pass: 0 -> y = x@Wl^T ; 1 -> z = x@Wr^T + b
// ---------------------------------------------------------------------------
template <int IN, int OUT>
__global__ void __launch_bounds__(256) transform2_kernel(
    const float* __restrict__ x, const float* __restrict__ Wl,
    const float* __restrict__ Wr, const float* __restrict__ bias,
    float* __restrict__ y, float* __restrict__ z)
{
    __shared__ __align__(16) float sW[IN * OUT];   // [k][o]
    __shared__ float sb[OUT];
    const bool zpass = (blockIdx.y == 1);
    const float* W = zpass ? Wr : Wl;
    for (int i = threadIdx.x; i < IN * OUT; i += 256) {
        int o = i / IN, k = i - o * IN;
        sW[k * OUT + o] = W[i];
    }
    if (threadIdx.x < OUT) sb[threadIdx.x] = zpass ? bias[threadIdx.x] : 0.0f;
    __syncthreads();

    int node = blockIdx.x * 256 + threadIdx.x;
    if (node >= NN) return;

    float acc[OUT];
#pragma unroll
    for (int o = 0; o < OUT; o++) acc[o] = sb[o];

    const float4* xr = reinterpret_cast<const float4*>(x + (size_t)node * IN);
#pragma unroll
    for (int k4 = 0; k4 < IN / 4; k4++) {
        float4 xv = xr[k4];
#pragma unroll
        for (int o = 0; o < OUT; o++) {
            acc[o] = fmaf(xv.x, sW[(4 * k4 + 0) * OUT + o], acc[o]);
            acc[o] = fmaf(xv.y, sW[(4 * k4 + 1) * OUT + o], acc[o]);
            acc[o] = fmaf(xv.z, sW[(4 * k4 + 2) * OUT + o], acc[o]);
            acc[o] = fmaf(xv.w, sW[(4 * k4 + 3) * OUT + o], acc[o]);
        }
    }

    float* outp = zpass ? z : y;
    float4* orow = reinterpret_cast<float4*>(outp + (size_t)node * OUT);
#pragma unroll
    for (int j = 0; j < OUT / 4; j++)
        orow[j] = make_float4(acc[4 * j], acc[4 * j + 1], acc[4 * j + 2], acc[4 * j + 3]);
}

// ---------------------------------------------------------------------------
// Aggregate+finalize: GROUP = OUT/4 lanes per node; lane g owns float4 #g.
// One 64B (OUT=16) / 32B (OUT=8) coalesced row read per edge; csr index
// broadcast within the group. No atomics; deg = off[n+1]-off[n].
// ---------------------------------------------------------------------------
template <int OUT, bool LOGSOFTMAX>
__global__ void __launch_bounds__(256) aggregate_kernel(
    const int* __restrict__ off, const int* __restrict__ csr,
    const float* __restrict__ y, const float* __restrict__ z,
    float* __restrict__ h)
{
    constexpr int GROUP = OUT / 4;
    int tid = blockIdx.x * blockDim.x + threadIdx.x;
    int node = tid / GROUP;
    int g = tid % GROUP;
    if (node >= NN) return;

    int beg = __ldg(off + node);
    int end = __ldg(off + node + 1);

    const float4* y4 = reinterpret_cast<const float4*>(y);
    float4 acc = make_float4(0.f, 0.f, 0.f, 0.f);

    int i = beg;
    for (; i + 4 <= end; i += 4) {
        int s0 = __ldg(csr + i + 0);
        int s1 = __ldg(csr + i + 1);
        int s2 = __ldg(csr + i + 2);
        int s3 = __ldg(csr + i + 3);
        float4 v0 = y4[(size_t)s0 * GROUP + g];
        float4 v1 = y4[(size_t)s1 * GROUP + g];
        float4 v2 = y4[(size_t)s2 * GROUP + g];
        float4 v3 = y4[(size_t)s3 * GROUP + g];
        acc.x += (v0.x + v1.x) + (v2.x + v3.x);
        acc.y += (v0.y + v1.y) + (v2.y + v3.y);
        acc.z += (v0.z + v1.z) + (v2.z + v3.z);
        acc.w += (v0.w + v1.w) + (v2.w + v3.w);
    }
    for (; i < end; i++) {
        float4 v = y4[(size_t)__ldg(csr + i) * GROUP + g];
        acc.x += v.x; acc.y += v.y; acc.z += v.z; acc.w += v.w;
    }

    float inv = 1.0f / fmaxf((float)(end - beg), 1.0f);
    const float4* z4 = reinterpret_cast<const float4*>(z);
    float4 zz = z4[(size_t)node * GROUP + g];
    float4 v;
    v.x = elu_f(fmaf(acc.x, inv, zz.x));
    v.y = elu_f(fmaf(acc.y, inv, zz.y));
    v.z = elu_f(fmaf(acc.z, inv, zz.z));
    v.w = elu_f(fmaf(acc.w, inv, zz.w));

    if (LOGSOFTMAX) {
        // OUT=8 -> GROUP=2; reduce 4 local + pair lane (width 2, pairs aligned)
        float m = fmaxf(fmaxf(v.x, v.y), fmaxf(v.z, v.w));
        m = fmaxf(m, __shfl_xor_sync(0xffffffff, m, 1, 2));
        float s = expf(v.x - m) + expf(v.y - m) + expf(v.z - m) + expf(v.w - m);
        s += __shfl_xor_sync(0xffffffff, s, 1, 2);
        float ls = m + logf(s);
        v.x -= ls; v.y -= ls; v.z -= ls; v.w -= ls;
    }

    float4* h4 = reinterpret_cast<float4*>(h);
    h4[(size_t)node * GROUP + g] = v;
}

// ---------------------------------------------------------------------------
extern "C" void kernel_launch(void* const* d_in, const int* in_sizes, int n_in,
                              void* d_out, int out_size)
{
    (void)in_sizes; (void)n_in; (void)out_size;

    const float* x   = (const float*)d_in[0];
    const int*   ei  = (const int*)d_in[1];   // int32 (JAX x64-disabled)
    const float* W1l = (const float*)d_in[2];
    const float* W1r = (const float*)d_in[3];
    const float* b1  = (const float*)d_in[4];
    const float* W2l = (const float*)d_in[5];
    const float* W2r = (const float*)d_in[6];
    const float* b2  = (const float*)d_in[7];
    const float* W3l = (const float*)d_in[8];
    const float* W3r = (const float*)d_in[9];
    const float* b3  = (const float*)d_in[10];
    float* out = (float*)d_out;

    const int* src = ei;
    const int* dst = ei + NE;

    float *py, *pz, *ph;
    int *pcnt, *poff, *pcur, *pcsr, *ppart;
    cudaGetSymbolAddress((void**)&py,   g_y);
    cudaGetSymbolAddress((void**)&pz,   g_z);
    cudaGetSymbolAddress((void**)&ph,   g_h);
    cudaGetSymbolAddress((void**)&pcnt, g_cnt);
    cudaGetSymbolAddress((void**)&poff, g_off);
    cudaGetSymbolAddress((void**)&pcur, g_cur);
    cudaGetSymbolAddress((void**)&pcsr, g_csr);
    cudaGetSymbolAddress((void**)&ppart, g_part);

    const int nbN = (NN + 255) / 256;
    const int nbE = (NE + 255) / 256;

    // ---- CSR build (graph reused by all 3 layers) ----
    cudaMemsetAsync(pcnt, 0, NN * sizeof(int));
    hist_kernel<<<nbE, 256>>>(dst, pcnt);
    scan1_kernel<<<NCHUNK, 256>>>(pcnt, ppart);
    scan2_kernel<<<1, 32>>>(ppart);
    scan3_kernel<<<NCHUNK, 256>>>(pcnt, ppart, poff, pcur);
    place_kernel<<<nbE, 256>>>(src, dst, pcur, pcsr);

    // ---- Layer 1: 48 -> 16 ----
    transform2_kernel<48, 16><<<dim3(nbN, 2), 256>>>(x, W1l, W1r, b1, py, pz);
    aggregate_kernel<16, false><<<(NN * 4 + 255) / 256, 256>>>(poff, pcsr, py, pz, ph);

    // ---- Layer 2: 16 -> 16 ----
    transform2_kernel<16, 16><<<dim3(nbN, 2), 256>>>(ph, W2l, W2r, b2, py, pz);
    aggregate_kernel<16, false><<<(NN * 4 + 255) / 256, 256>>>(poff, pcsr, py, pz, ph);

    // ---- Layer 3: 16 -> 8 (+ log_softmax) ----
    transform2_kernel<16, 8><<<dim3(nbN, 2), 256>>>(ph, W3l, W3r, b3, py, pz);
    aggregate_kernel<8, true><<<(NN * 2 + 255) / 256, 256>>>(poff, pcsr, py, pz, out);
}

// round 5
// speedup vs baseline: 1.2702x; 1.2702x over previous
#include <cuda_runtime.h>
#include <math.h>

#define NN 100000
#define NE 1600000
#define SCAN_CHUNK 1024
#define NCHUNK ((NN + SCAN_CHUNK - 1) / SCAN_CHUNK)   // 98

// ---------------- scratch (allocation-free) ----------------
__device__ __align__(16) float g_y[NN * 16];   // W_l-projected features
__device__ __align__(16) float g_z[NN * 16];   // W_r-projected + bias
__device__ __align__(16) float g_h[NN * 16];   // layer output
__device__ int g_cnt[NN];                      // in-degree histogram
__device__ int g_off[NN + 1];                  // CSR row offsets
__device__ int g_cur[NN];                      // placement cursors
__device__ int g_csr[NE];                      // CSR src indices (grouped by dst)
__device__ int g_part[NCHUNK];                 // scan partials

__device__ __forceinline__ float elu_f(float v) {
    return v > 0.0f ? v : expm1f(v);
}

// ---------------------------------------------------------------------------
// CSR build: memset -> histogram -> 3-step scan -> place
// ---------------------------------------------------------------------------
__global__ void hist_kernel(const int* __restrict__ dst, int* __restrict__ cnt) {
    int e = blockIdx.x * blockDim.x + threadIdx.x;
    if (e < NE) atomicAdd(cnt + __ldg(dst + e), 1);   // RED (no return)
}

__global__ void scan1_kernel(const int* __restrict__ cnt, int* __restrict__ part) {
    __shared__ int red[256];
    int b = blockIdx.x;
    int sum = 0;
    for (int i = threadIdx.x; i < SCAN_CHUNK; i += 256) {
        int idx = b * SCAN_CHUNK + i;
        if (idx < NN) sum += cnt[idx];
    }
    red[threadIdx.x] = sum;
    __syncthreads();
    for (int s = 128; s > 0; s >>= 1) {
        if (threadIdx.x < s) red[threadIdx.x] += red[threadIdx.x + s];
        __syncthreads();
    }
    if (threadIdx.x == 0) part[b] = red[0];
}

// Parallel exclusive scan of NCHUNK(=98) partials: 1 warp, 4 elems/lane.
__global__ void scan2_kernel(int* __restrict__ part) {
    int lane = threadIdx.x;
    int base = lane * 4;
    int v[4];
#pragma unroll
    for (int k = 0; k < 4; k++)
        v[k] = (base + k < NCHUNK) ? part[base + k] : 0;
    int s = v[0] + v[1] + v[2] + v[3];
    int sc = s;
#pragma unroll
    for (int o = 1; o < 32; o <<= 1) {
        int n = __shfl_up_sync(0xffffffff, sc, o);
        if (lane >= o) sc += n;
    }
    int excl = sc - s;
#pragma unroll
    for (int k = 0; k < 4; k++) {
        if (base + k < NCHUNK) part[base + k] = excl;
        excl += v[k];
    }
}

__global__ void scan3_kernel(const int* __restrict__ cnt, const int* __restrict__ part,
                             int* __restrict__ off, int* __restrict__ cur) {
    __shared__ int wsum[8];
    int b = blockIdx.x, t = threadIdx.x;
    int gbase = b * SCAN_CHUNK + t * 4;
    int v0 = (gbase + 0 < NN) ? cnt[gbase + 0] : 0;
    int v1 = (gbase + 1 < NN) ? cnt[gbase + 1] : 0;
    int v2 = (gbase + 2 < NN) ? cnt[gbase + 2] : 0;
    int v3 = (gbase + 3 < NN) ? cnt[gbase + 3] : 0;
    int s = v0 + v1 + v2 + v3;

    int lane = t & 31, wid = t >> 5;
    int sc = s;
#pragma unroll
    for (int o = 1; o < 32; o <<= 1) {
        int n = __shfl_up_sync(0xffffffff, sc, o);
        if (lane >= o) sc += n;
    }
    if (lane == 31) wsum[wid] = sc;
    __syncthreads();
    if (wid == 0) {
        int ws = (lane < 8) ? wsum[lane] : 0;
#pragma unroll
        for (int o = 1; o < 8; o <<= 1) {
            int n = __shfl_up_sync(0xffffffff, ws, o);
            if (lane >= o) ws += n;
        }
        if (lane < 8) wsum[lane] = ws;   // inclusive warp sums
    }
    __syncthreads();

    int excl = sc - s + (wid > 0 ? wsum[wid - 1] : 0) + part[b];
    if (gbase + 0 < NN) { off[gbase + 0] = excl; cur[gbase + 0] = excl; } excl += v0;
    if (gbase + 1 < NN) { off[gbase + 1] = excl; cur[gbase + 1] = excl; } excl += v1;
    if (gbase + 2 < NN) { off[gbase + 2] = excl; cur[gbase + 2] = excl; } excl += v2;
    if (gbase + 3 < NN) { off[gbase + 3] = excl; cur[gbase + 3] = excl; }
    if (b == 0 && t == 0) off[NN] = NE;
}

__global__ void place_kernel(const int* __restrict__ src, const int* __restrict__ dst,
                             int* __restrict__ cur, int* __restrict__ csr) {
    int e = blockIdx.x * blockDim.x + threadIdx.x;
    if (e >= NE) return;
    int d = __ldg(dst + e);
    int p = atomicAdd(cur + d, 1);
    csr[p] = __ldg(src + e);
}

// ---------------------------------------------------------------------------
// Transform: gridDim.y selects pass: 0 -> y = x@Wl^T ; 1 -> z = x@Wr^T + b
// ---------------------------------------------------------------------------
template <int IN, int OUT>
__global__ void __launch_bounds__(256) transform2_kernel(
    const float* __restrict__ x, const float* __restrict__ Wl,
    const float* __restrict__ Wr, const float* __restrict__ bias,
    float* __restrict__ y, float* __restrict__ z)
{
    __shared__ __align__(16) float sW[IN * OUT];   // [k][o]
    __shared__ float sb[OUT];
    const bool zpass = (blockIdx.y == 1);
    const float* W = zpass ? Wr : Wl;
    for (int i = threadIdx.x; i < IN * OUT; i += 256) {
        int o = i / IN, k = i - o * IN;
        sW[k * OUT + o] = W[i];
    }
    if (threadIdx.x < OUT) sb[threadIdx.x] = zpass ? bias[threadIdx.x] : 0.0f;
    __syncthreads();

    int node = blockIdx.x * 256 + threadIdx.x;
    if (node >= NN) return;

    float acc[OUT];
#pragma unroll
    for (int o = 0; o < OUT; o++) acc[o] = sb[o];

    const float4* xr = reinterpret_cast<const float4*>(x + (size_t)node * IN);
#pragma unroll
    for (int k4 = 0; k4 < IN / 4; k4++) {
        float4 xv = xr[k4];
#pragma unroll
        for (int o = 0; o < OUT; o++) {
            acc[o] = fmaf(xv.x, sW[(4 * k4 + 0) * OUT + o], acc[o]);
            acc[o] = fmaf(xv.y, sW[(4 * k4 + 1) * OUT + o], acc[o]);
            acc[o] = fmaf(xv.z, sW[(4 * k4 + 2) * OUT + o], acc[o]);
            acc[o] = fmaf(xv.w, sW[(4 * k4 + 3) * OUT + o], acc[o]);
        }
    }

    float* outp = zpass ? z : y;
    float4* orow = reinterpret_cast<float4*>(outp + (size_t)node * OUT);
#pragma unroll
    for (int j = 0; j < OUT / 4; j++)
        orow[j] = make_float4(acc[4 * j], acc[4 * j + 1], acc[4 * j + 2], acc[4 * j + 3]);
}

// ---------------------------------------------------------------------------
// Aggregate+finalize (R3-proven form): OUT lanes per node; lane l owns
// feature l. Each edge -> coalesced 64B/32B row read; high warp count for
// latency hiding. h = ELU(mean + z); optional width-OUT log_softmax.
// ---------------------------------------------------------------------------
template <int OUT, bool LOGSOFTMAX>
__global__ void __launch_bounds__(256) aggregate_kernel(
    const int* __restrict__ off, const int* __restrict__ csr,
    const float* __restrict__ y, const float* __restrict__ z,
    float* __restrict__ h)
{
    int lane = threadIdx.x % OUT;
    int node = (blockIdx.x * blockDim.x + threadIdx.x) / OUT;
    if (node >= NN) return;

    int beg = __ldg(off + node);
    int end = __ldg(off + node + 1);

    float acc = 0.0f;
    int i = beg;
    for (; i + 4 <= end; i += 4) {
        int s0 = __ldg(csr + i + 0);
        int s1 = __ldg(csr + i + 1);
        int s2 = __ldg(csr + i + 2);
        int s3 = __ldg(csr + i + 3);
        float v0 = __ldg(y + (size_t)s0 * OUT + lane);
        float v1 = __ldg(y + (size_t)s1 * OUT + lane);
        float v2 = __ldg(y + (size_t)s2 * OUT + lane);
        float v3 = __ldg(y + (size_t)s3 * OUT + lane);
        acc += (v0 + v1) + (v2 + v3);
    }
    for (; i < end; i++)
        acc += __ldg(y + (size_t)__ldg(csr + i) * OUT + lane);

    float deg = (float)(end - beg);
    acc /= fmaxf(deg, 1.0f);
    acc += __ldg(z + (size_t)node * OUT + lane);
    float v = elu_f(acc);

    if (LOGSOFTMAX) {
        float m = v;
#pragma unroll
        for (int o = OUT / 2; o >= 1; o >>= 1)
            m = fmaxf(m, __shfl_xor_sync(0xffffffff, m, o, OUT));
        float ex = expf(v - m);
        float s = ex;
#pragma unroll
        for (int o = OUT / 2; o >= 1; o >>= 1)
            s += __shfl_xor_sync(0xffffffff, s, o, OUT);
        v = v - m - logf(s);
    }

    h[(size_t)node * OUT + lane] = v;
}

// ---------------------------------------------------------------------------
extern "C" void kernel_launch(void* const* d_in, const int* in_sizes, int n_in,
                              void* d_out, int out_size)
{
    (void)in_sizes; (void)n_in; (void)out_size;

    const float* x   = (const float*)d_in[0];
    const int*   ei  = (const int*)d_in[1];   // int32 (JAX x64-disabled)
    const float* W1l = (const float*)d_in[2];
    const float* W1r = (const float*)d_in[3];
    const float* b1  = (const float*)d_in[4];
    const float* W2l = (const float*)d_in[5];
    const float* W2r = (const float*)d_in[6];
    const float* b2  = (const float*)d_in[7];
    const float* W3l = (const float*)d_in[8];
    const float* W3r = (const float*)d_in[9];
    const float* b3  = (const float*)d_in[10];
    float* out = (float*)d_out;

    const int* src = ei;
    const int* dst = ei + NE;

    float *py, *pz, *ph;
    int *pcnt, *poff, *pcur, *pcsr, *ppart;
    cudaGetSymbolAddress((void**)&py,   g_y);
    cudaGetSymbolAddress((void**)&pz,   g_z);
    cudaGetSymbolAddress((void**)&ph,   g_h);
    cudaGetSymbolAddress((void**)&pcnt, g_cnt);
    cudaGetSymbolAddress((void**)&poff, g_off);
    cudaGetSymbolAddress((void**)&pcur, g_cur);
    cudaGetSymbolAddress((void**)&pcsr, g_csr);
    cudaGetSymbolAddress((void**)&ppart, g_part);

    const int nbN = (NN + 255) / 256;
    const int nbE = (NE + 255) / 256;

    // ---- CSR build (graph reused by all 3 layers) ----
    cudaMemsetAsync(pcnt, 0, NN * sizeof(int));
    hist_kernel<<<nbE, 256>>>(dst, pcnt);
    scan1_kernel<<<NCHUNK, 256>>>(pcnt, ppart);
    scan2_kernel<<<1, 32>>>(ppart);
    scan3_kernel<<<NCHUNK, 256>>>(pcnt, ppart, poff, pcur);
    place_kernel<<<nbE, 256>>>(src, dst, pcur, pcsr);

    // ---- Layer 1: 48 -> 16 ----
    transform2_kernel<48, 16><<<dim3(nbN, 2), 256>>>(x, W1l, W1r, b1, py, pz);
    aggregate_kernel<16, false><<<(NN * 16 + 255) / 256, 256>>>(poff, pcsr, py, pz, ph);

    // ---- Layer 2: 16 -> 16 ----
    transform2_kernel<16, 16><<<dim3(nbN, 2), 256>>>(ph, W2l, W2r, b2, py, pz);
    aggregate_kernel<16, false><<<(NN * 16 + 255) / 256, 256>>>(poff, pcsr, py, pz, ph);

    // ---- Layer 3: 16 -> 8 (+ log_softmax) ----
    transform2_kernel<16, 8><<<dim3(nbN, 2), 256>>>(ph, W3l, W3r, b3, py, pz);
    aggregate_kernel<8, true><<<(NN * 8 + 255) / 256, 256>>>(poff, pcsr, py, pz, out);
}

// round 6
// speedup vs baseline: 1.2705x; 1.0002x over previous
#include <cuda_runtime.h>
#include <math.h>

#define NN 100000
#define NE 1600000
#define SCAN_CHUNK 1024
#define NCHUNK ((NN + SCAN_CHUNK - 1) / SCAN_CHUNK)   // 98

// ---------------- scratch (allocation-free) ----------------
__device__ __align__(16) float g_yA[NN * 16];
__device__ __align__(16) float g_zA[NN * 16];
__device__ __align__(16) float g_yB[NN * 16];
__device__ __align__(16) float g_zB[NN * 16];
__device__ int g_cnt[NN];                      // in-degree histogram
__device__ int g_off[NN + 1];                  // CSR row offsets
__device__ int g_cur[NN];                      // placement cursors
__device__ int g_csr[NE];                      // CSR src indices (grouped by dst)
__device__ int g_part[NCHUNK];                 // scan partials

__device__ __forceinline__ float elu_f(float v) {
    return v > 0.0f ? v : expm1f(v);
}

// ---------------------------------------------------------------------------
// CSR build: memset -> histogram -> 3-step scan -> place
// ---------------------------------------------------------------------------
__global__ void hist_kernel(const int* __restrict__ dst, int* __restrict__ cnt) {
    int e = blockIdx.x * blockDim.x + threadIdx.x;
    if (e < NE) atomicAdd(cnt + __ldg(dst + e), 1);   // RED (no return)
}

__global__ void scan1_kernel(const int* __restrict__ cnt, int* __restrict__ part) {
    __shared__ int red[256];
    int b = blockIdx.x;
    int sum = 0;
    for (int i = threadIdx.x; i < SCAN_CHUNK; i += 256) {
        int idx = b * SCAN_CHUNK + i;
        if (idx < NN) sum += cnt[idx];
    }
    red[threadIdx.x] = sum;
    __syncthreads();
    for (int s = 128; s > 0; s >>= 1) {
        if (threadIdx.x < s) red[threadIdx.x] += red[threadIdx.x + s];
        __syncthreads();
    }
    if (threadIdx.x == 0) part[b] = red[0];
}

// Parallel exclusive scan of NCHUNK(=98) partials: 1 warp, 4 elems/lane.
__global__ void scan2_kernel(int* __restrict__ part) {
    int lane = threadIdx.x;
    int base = lane * 4;
    int v[4];
#pragma unroll
    for (int k = 0; k < 4; k++)
        v[k] = (base + k < NCHUNK) ? part[base + k] : 0;
    int s = v[0] + v[1] + v[2] + v[3];
    int sc = s;
#pragma unroll
    for (int o = 1; o < 32; o <<= 1) {
        int n = __shfl_up_sync(0xffffffff, sc, o);
        if (lane >= o) sc += n;
    }
    int excl = sc - s;
#pragma unroll
    for (int k = 0; k < 4; k++) {
        if (base + k < NCHUNK) part[base + k] = excl;
        excl += v[k];
    }
}

__global__ void scan3_kernel(const int* __restrict__ cnt, const int* __restrict__ part,
                             int* __restrict__ off, int* __restrict__ cur) {
    __shared__ int wsum[8];
    int b = blockIdx.x, t = threadIdx.x;
    int gbase = b * SCAN_CHUNK + t * 4;
    int v0 = (gbase + 0 < NN) ? cnt[gbase + 0] : 0;
    int v1 = (gbase + 1 < NN) ? cnt[gbase + 1] : 0;
    int v2 = (gbase + 2 < NN) ? cnt[gbase + 2] : 0;
    int v3 = (gbase + 3 < NN) ? cnt[gbase + 3] : 0;
    int s = v0 + v1 + v2 + v3;

    int lane = t & 31, wid = t >> 5;
    int sc = s;
#pragma unroll
    for (int o = 1; o < 32; o <<= 1) {
        int n = __shfl_up_sync(0xffffffff, sc, o);
        if (lane >= o) sc += n;
    }
    if (lane == 31) wsum[wid] = sc;
    __syncthreads();
    if (wid == 0) {
        int ws = (lane < 8) ? wsum[lane] : 0;
#pragma unroll
        for (int o = 1; o < 8; o <<= 1) {
            int n = __shfl_up_sync(0xffffffff, ws, o);
            if (lane >= o) ws += n;
        }
        if (lane < 8) wsum[lane] = ws;   // inclusive warp sums
    }
    __syncthreads();

    int excl = sc - s + (wid > 0 ? wsum[wid - 1] : 0) + part[b];
    if (gbase + 0 < NN) { off[gbase + 0] = excl; cur[gbase + 0] = excl; } excl += v0;
    if (gbase + 1 < NN) { off[gbase + 1] = excl; cur[gbase + 1] = excl; } excl += v1;
    if (gbase + 2 < NN) { off[gbase + 2] = excl; cur[gbase + 2] = excl; } excl += v2;
    if (gbase + 3 < NN) { off[gbase + 3] = excl; cur[gbase + 3] = excl; }
    if (b == 0 && t == 0) off[NN] = NE;
}

__global__ void place_kernel(const int* __restrict__ src, const int* __restrict__ dst,
                             int* __restrict__ cur, int* __restrict__ csr) {
    int e = blockIdx.x * blockDim.x + threadIdx.x;
    if (e >= NE) return;
    int d = __ldg(dst + e);
    int p = atomicAdd(cur + d, 1);
    csr[p] = __ldg(src + e);
}

// ---------------------------------------------------------------------------
// Transform (layer 1 only): gridDim.y: 0 -> y = x@Wl^T ; 1 -> z = x@Wr^T + b
// ---------------------------------------------------------------------------
template <int IN, int OUT>
__global__ void __launch_bounds__(256) transform2_kernel(
    const float* __restrict__ x, const float* __restrict__ Wl,
    const float* __restrict__ Wr, const float* __restrict__ bias,
    float* __restrict__ y, float* __restrict__ z)
{
    __shared__ __align__(16) float sW[IN * OUT];   // [k][o]
    __shared__ float sb[OUT];
    const bool zpass = (blockIdx.y == 1);
    const float* W = zpass ? Wr : Wl;
    for (int i = threadIdx.x; i < IN * OUT; i += 256) {
        int o = i / IN, k = i - o * IN;
        sW[k * OUT + o] = W[i];
    }
    if (threadIdx.x < OUT) sb[threadIdx.x] = zpass ? bias[threadIdx.x] : 0.0f;
    __syncthreads();

    int node = blockIdx.x * 256 + threadIdx.x;
    if (node >= NN) return;

    float acc[OUT];
#pragma unroll
    for (int o = 0; o < OUT; o++) acc[o] = sb[o];

    const float4* xr = reinterpret_cast<const float4*>(x + (size_t)node * IN);
#pragma unroll
    for (int k4 = 0; k4 < IN / 4; k4++) {
        float4 xv = xr[k4];
#pragma unroll
        for (int o = 0; o < OUT; o++) {
            acc[o] = fmaf(xv.x, sW[(4 * k4 + 0) * OUT + o], acc[o]);
            acc[o] = fmaf(xv.y, sW[(4 * k4 + 1) * OUT + o], acc[o]);
            acc[o] = fmaf(xv.z, sW[(4 * k4 + 2) * OUT + o], acc[o]);
            acc[o] = fmaf(xv.w, sW[(4 * k4 + 3) * OUT + o], acc[o]);
        }
    }

    float* outp = zpass ? z : y;
    float4* orow = reinterpret_cast<float4*>(outp + (size_t)node * OUT);
#pragma unroll
    for (int j = 0; j < OUT / 4; j++)
        orow[j] = make_float4(acc[4 * j], acc[4 * j + 1], acc[4 * j + 2], acc[4 * j + 3]);
}

// ---------------------------------------------------------------------------
// Fused aggregate + finalize + NEXT-layer transform.
// 16 lanes per node (input width 16). After ELU, the 16-lane group holds the
// full h-row in registers; next layer's y/z (width OUT_NEXT) computed via
// width-16 shfl broadcasts + FMA against smem-transposed weights.
// Removes the h round-trip and 2 transform launches.
// ---------------------------------------------------------------------------
template <int OUT_NEXT>
__global__ void __launch_bounds__(256) agg_xform_kernel(
    const int* __restrict__ off, const int* __restrict__ csr,
    const float* __restrict__ y, const float* __restrict__ z,
    const float* __restrict__ Wl, const float* __restrict__ Wr,
    const float* __restrict__ bias,
    float* __restrict__ yn, float* __restrict__ zn)
{
    __shared__ float sWl[16 * OUT_NEXT];   // [k][o]
    __shared__ float sWr[16 * OUT_NEXT];
    __shared__ float sb[OUT_NEXT];
    for (int i = threadIdx.x; i < 16 * OUT_NEXT; i += 256) {
        int o = i / 16, k = i - o * 16;
        sWl[k * OUT_NEXT + o] = Wl[i];
        sWr[k * OUT_NEXT + o] = Wr[i];
    }
    if (threadIdx.x < OUT_NEXT) sb[threadIdx.x] = bias[threadIdx.x];
    __syncthreads();

    int lane = threadIdx.x & 15;
    int node = (blockIdx.x * 256 + threadIdx.x) >> 4;   // grid exact: NN*16 % 256 == 0

    int beg = __ldg(off + node);
    int end = __ldg(off + node + 1);

    float acc = 0.0f;
    int i = beg;
    for (; i + 4 <= end; i += 4) {
        int s0 = __ldg(csr + i + 0);
        int s1 = __ldg(csr + i + 1);
        int s2 = __ldg(csr + i + 2);
        int s3 = __ldg(csr + i + 3);
        float v0 = __ldg(y + (size_t)s0 * 16 + lane);
        float v1 = __ldg(y + (size_t)s1 * 16 + lane);
        float v2 = __ldg(y + (size_t)s2 * 16 + lane);
        float v3 = __ldg(y + (size_t)s3 * 16 + lane);
        acc += (v0 + v1) + (v2 + v3);
    }
    for (; i < end; i++)
        acc += __ldg(y + (size_t)__ldg(csr + i) * 16 + lane);

    float inv = 1.0f / fmaxf((float)(end - beg), 1.0f);
    float v = elu_f(fmaf(acc, inv, __ldg(z + (size_t)node * 16 + lane)));

    // next-layer transform via shfl broadcast of the h-row
    float accY = 0.0f;
    float accZ = (lane < OUT_NEXT) ? sb[lane] : 0.0f;
#pragma unroll
    for (int k = 0; k < 16; k++) {
        float hk = __shfl_sync(0xffffffffu, v, k, 16);
        if (lane < OUT_NEXT) {
            accY = fmaf(hk, sWl[k * OUT_NEXT + lane], accY);
            accZ = fmaf(hk, sWr[k * OUT_NEXT + lane], accZ);
        }
    }
    if (lane < OUT_NEXT) {
        yn[(size_t)node * OUT_NEXT + lane] = accY;
        zn[(size_t)node * OUT_NEXT + lane] = accZ;
    }
}

// ---------------------------------------------------------------------------
// Final aggregate (width 8) + ELU + log_softmax.
// ---------------------------------------------------------------------------
__global__ void __launch_bounds__(256) agg_final_kernel(
    const int* __restrict__ off, const int* __restrict__ csr,
    const float* __restrict__ y, const float* __restrict__ z,
    float* __restrict__ out)
{
    int lane = threadIdx.x & 7;
    int node = (blockIdx.x * 256 + threadIdx.x) >> 3;   // grid exact: NN*8 % 256 == 0

    int beg = __ldg(off + node);
    int end = __ldg(off + node + 1);

    float acc = 0.0f;
    int i = beg;
    for (; i + 4 <= end; i += 4) {
        int s0 = __ldg(csr + i + 0);
        int s1 = __ldg(csr + i + 1);
        int s2 = __ldg(csr + i + 2);
        int s3 = __ldg(csr + i + 3);
        float v0 = __ldg(y + (size_t)s0 * 8 + lane);
        float v1 = __ldg(y + (size_t)s1 * 8 + lane);
        float v2 = __ldg(y + (size_t)s2 * 8 + lane);
        float v3 = __ldg(y + (size_t)s3 * 8 + lane);
        acc += (v0 + v1) + (v2 + v3);
    }
    for (; i < end; i++)
        acc += __ldg(y + (size_t)__ldg(csr + i) * 8 + lane);

    float inv = 1.0f / fmaxf((float)(end - beg), 1.0f);
    float v = elu_f(fmaf(acc, inv, __ldg(z + (size_t)node * 8 + lane)));

    float m = v;
#pragma unroll
    for (int o = 4; o >= 1; o >>= 1)
        m = fmaxf(m, __shfl_xor_sync(0xffffffff, m, o, 8));
    float ex = expf(v - m);
    float s = ex;
#pragma unroll
    for (int o = 4; o >= 1; o >>= 1)
        s += __shfl_xor_sync(0xffffffff, s, o, 8);
    v = v - m - logf(s);

    out[(size_t)node * 8 + lane] = v;
}

// ---------------------------------------------------------------------------
extern "C" void kernel_launch(void* const* d_in, const int* in_sizes, int n_in,
                              void* d_out, int out_size)
{
    (void)in_sizes; (void)n_in; (void)out_size;

    const float* x   = (const float*)d_in[0];
    const int*   ei  = (const int*)d_in[1];   // int32 (JAX x64-disabled)
    const float* W1l = (const float*)d_in[2];
    const float* W1r = (const float*)d_in[3];
    const float* b1  = (const float*)d_in[4];
    const float* W2l = (const float*)d_in[5];
    const float* W2r = (const float*)d_in[6];
    const float* b2  = (const float*)d_in[7];
    const float* W3l = (const float*)d_in[8];
    const float* W3r = (const float*)d_in[9];
    const float* b3  = (const float*)d_in[10];
    float* out = (float*)d_out;

    const int* src = ei;
    const int* dst = ei + NE;

    float *pyA, *pzA, *pyB, *pzB;
    int *pcnt, *poff, *pcur, *pcsr, *ppart;
    cudaGetSymbolAddress((void**)&pyA,  g_yA);
    cudaGetSymbolAddress((void**)&pzA,  g_zA);
    cudaGetSymbolAddress((void**)&pyB,  g_yB);
    cudaGetSymbolAddress((void**)&pzB,  g_zB);
    cudaGetSymbolAddress((void**)&pcnt, g_cnt);
    cudaGetSymbolAddress((void**)&poff, g_off);
    cudaGetSymbolAddress((void**)&pcur, g_cur);
    cudaGetSymbolAddress((void**)&pcsr, g_csr);
    cudaGetSymbolAddress((void**)&ppart, g_part);

    const int nbN = (NN + 255) / 256;
    const int nbE = (NE + 255) / 256;

    // ---- CSR build (graph reused by all 3 layers) ----
    cudaMemsetAsync(pcnt, 0, NN * sizeof(int));
    hist_kernel<<<nbE, 256>>>(dst, pcnt);
    scan1_kernel<<<NCHUNK, 256>>>(pcnt, ppart);
    scan2_kernel<<<1, 32>>>(ppart);
    scan3_kernel<<<NCHUNK, 256>>>(pcnt, ppart, poff, pcur);
    place_kernel<<<nbE, 256>>>(src, dst, pcur, pcsr);

    // ---- Layer 1 transform: x(48) -> yA,zA (16) ----
    transform2_kernel<48, 16><<<dim3(nbN, 2), 256>>>(x, W1l, W1r, b1, pyA, pzA);

    // ---- Layer 1 agg + layer 2 transform: -> yB,zB (16) ----
    agg_xform_kernel<16><<<NN * 16 / 256, 256>>>(poff, pcsr, pyA, pzA,
                                                 W2l, W2r, b2, pyB, pzB);

    // ---- Layer 2 agg + layer 3 transform: -> yA,zA (8) ----
    agg_xform_kernel<8><<<NN * 16 / 256, 256>>>(poff, pcsr, pyB, pzB,
                                                W3l, W3r, b3, pyA, pzA);

    // ---- Layer 3 agg + log_softmax ----
    agg_final_kernel<<<NN * 8 / 256, 256>>>(poff, pcsr, pyA, pzA, out);
}

// round 7
// speedup vs baseline: 1.3438x; 1.0577x over previous
#include <cuda_runtime.h>
#include <math.h>

#define NN 100000
#define NE 1600000
#define SCAN_CHUNK 1024
#define NCHUNK ((NN + SCAN_CHUNK - 1) / SCAN_CHUNK)   // 98

// ---------------- scratch (allocation-free) ----------------
__device__ __align__(16) float g_yA[NN * 16];
__device__ __align__(16) float g_zA[NN * 16];
__device__ __align__(16) float g_yB[NN * 16];
__device__ __align__(16) float g_zB[NN * 16];
__device__ int g_cnt[NN];                        // in-degree histogram
__device__ int g_off[NN + 1];                    // CSR row offsets
__device__ int g_cur[NN];                        // placement cursors
__device__ int g_csr[NE];                        // CSR src indices (grouped by dst)
__device__ unsigned long long g_state[NCHUNK];   // lookback: (flag<<32)|sum

__device__ __forceinline__ float elu_f(float v) {
    return v > 0.0f ? v : expm1f(v);
}

// ---------------------------------------------------------------------------
// CSR build: memset -> histogram -> single-pass scan (decoupled lookback) -> place
// ---------------------------------------------------------------------------
__global__ void hist_kernel(const int* __restrict__ dst, int* __restrict__ cnt) {
    int e = blockIdx.x * blockDim.x + threadIdx.x;
    if (e < NE) atomicAdd(cnt + __ldg(dst + e), 1);   // RED (no return)
}

// One launch: per-block local scan + decoupled lookback across 98 blocks
// (all co-resident on 148 SMs -> spin-wait is deadlock-free).
__global__ void __launch_bounds__(256) scan_onepass_kernel(
    const int* __restrict__ cnt, int* __restrict__ off, int* __restrict__ cur)
{
    __shared__ int wsum[8];
    __shared__ int s_base;
    int b = blockIdx.x, t = threadIdx.x;
    int gbase = b * SCAN_CHUNK + t * 4;
    int v0 = (gbase + 0 < NN) ? cnt[gbase + 0] : 0;
    int v1 = (gbase + 1 < NN) ? cnt[gbase + 1] : 0;
    int v2 = (gbase + 2 < NN) ? cnt[gbase + 2] : 0;
    int v3 = (gbase + 3 < NN) ? cnt[gbase + 3] : 0;
    int s = v0 + v1 + v2 + v3;

    int lane = t & 31, wid = t >> 5;
    int sc = s;
#pragma unroll
    for (int o = 1; o < 32; o <<= 1) {
        int n = __shfl_up_sync(0xffffffff, sc, o);
        if (lane >= o) sc += n;
    }
    if (lane == 31) wsum[wid] = sc;
    __syncthreads();
    if (wid == 0) {
        int ws = (lane < 8) ? wsum[lane] : 0;
#pragma unroll
        for (int o = 1; o < 8; o <<= 1) {
            int n = __shfl_up_sync(0xffffffff, ws, o);
            if (lane >= o) ws += n;
        }
        if (lane < 8) wsum[lane] = ws;   // inclusive warp sums
    }
    __syncthreads();
    int total = wsum[7];

    if (b == 0) {
        if (t == 0) {
            atomicExch(&g_state[0], (2ULL << 32) | (unsigned long long)(unsigned)total);
            s_base = 0;
        }
    } else {
        if (t == 0)
            atomicExch(&g_state[b], (1ULL << 32) | (unsigned long long)(unsigned)total);
        if (wid == 0) {
            // warp-parallel lookback: lane L inspects predecessor b-1-L
            int sum = 0;
            int base_j = b - 1;
            while (true) {
                int j = base_j - lane;
                int flag, val;
                if (j >= 0) {
                    unsigned long long v;
                    do { v = *(volatile unsigned long long*)&g_state[j]; }
                    while ((unsigned)(v >> 32) == 0u);
                    flag = (int)(v >> 32);
                    val = (int)(unsigned)v;
                } else { flag = 2; val = 0; }
                unsigned m = __ballot_sync(0xffffffffu, flag == 2);
                int firstDone = (m == 0u) ? -1 : (__ffs(m) - 1);
                int contrib = (firstDone < 0 || lane <= firstDone) ? val : 0;
#pragma unroll
                for (int o = 16; o >= 1; o >>= 1)
                    contrib += __shfl_xor_sync(0xffffffffu, contrib, o);
                sum += contrib;
                if (firstDone >= 0) break;
                base_j -= 32;
            }
            if (lane == 0) {
                atomicExch(&g_state[b],
                           (2ULL << 32) | (unsigned long long)(unsigned)(sum + total));
                s_base = sum;
            }
        }
    }
    __syncthreads();

    int excl = sc - s + (wid > 0 ? wsum[wid - 1] : 0) + s_base;
    if (gbase + 0 < NN) { off[gbase + 0] = excl; cur[gbase + 0] = excl; } excl += v0;
    if (gbase + 1 < NN) { off[gbase + 1] = excl; cur[gbase + 1] = excl; } excl += v1;
    if (gbase + 2 < NN) { off[gbase + 2] = excl; cur[gbase + 2] = excl; } excl += v2;
    if (gbase + 3 < NN) { off[gbase + 3] = excl; cur[gbase + 3] = excl; }
    if (b == 0 && t == 0) off[NN] = NE;
}

__global__ void place_kernel(const int* __restrict__ src, const int* __restrict__ dst,
                             int* __restrict__ cur, int* __restrict__ csr) {
    int e = blockIdx.x * blockDim.x + threadIdx.x;
    if (e >= NE) return;
    int d = __ldg(dst + e);
    int p = atomicAdd(cur + d, 1);
    csr[p] = __ldg(src + e);
}

// ---------------------------------------------------------------------------
// Transform (layer 1 only): gridDim.y: 0 -> y = x@Wl^T ; 1 -> z = x@Wr^T + b
// ---------------------------------------------------------------------------
template <int IN, int OUT>
__global__ void __launch_bounds__(256) transform2_kernel(
    const float* __restrict__ x, const float* __restrict__ Wl,
    const float* __restrict__ Wr, const float* __restrict__ bias,
    float* __restrict__ y, float* __restrict__ z)
{
    __shared__ __align__(16) float sW[IN * OUT];   // [k][o]
    __shared__ float sb[OUT];
    const bool zpass = (blockIdx.y == 1);
    const float* W = zpass ? Wr : Wl;
    for (int i = threadIdx.x; i < IN * OUT; i += 256) {
        int o = i / IN, k = i - o * IN;
        sW[k * OUT + o] = W[i];
    }
    if (threadIdx.x < OUT) sb[threadIdx.x] = zpass ? bias[threadIdx.x] : 0.0f;
    __syncthreads();

    int node = blockIdx.x * 256 + threadIdx.x;
    if (node >= NN) return;

    float acc[OUT];
#pragma unroll
    for (int o = 0; o < OUT; o++) acc[o] = sb[o];

    const float4* xr = reinterpret_cast<const float4*>(x + (size_t)node * IN);
#pragma unroll
    for (int k4 = 0; k4 < IN / 4; k4++) {
        float4 xv = xr[k4];
#pragma unroll
        for (int o = 0; o < OUT; o++) {
            acc[o] = fmaf(xv.x, sW[(4 * k4 + 0) * OUT + o], acc[o]);
            acc[o] = fmaf(xv.y, sW[(4 * k4 + 1) * OUT + o], acc[o]);
            acc[o] = fmaf(xv.z, sW[(4 * k4 + 2) * OUT + o], acc[o]);
            acc[o] = fmaf(xv.w, sW[(4 * k4 + 3) * OUT + o], acc[o]);
        }
    }

    float* outp = zpass ? z : y;
    float4* orow = reinterpret_cast<float4*>(outp + (size_t)node * OUT);
#pragma unroll
    for (int j = 0; j < OUT / 4; j++)
        orow[j] = make_float4(acc[4 * j], acc[4 * j + 1], acc[4 * j + 2], acc[4 * j + 3]);
}

// ---------------------------------------------------------------------------
// Software-pipelined mean gather: prefetch next 4 csr indices while gathering
// the current 4 (breaks idx->gather serial chain).
// ---------------------------------------------------------------------------
template <int W>
__device__ __forceinline__ float gather_mean(
    const int* __restrict__ csr, const float* __restrict__ y,
    int beg, int end, int lane)
{
    float acc = 0.0f;
    int i = beg;
    int a0 = 0, a1 = 0, a2 = 0, a3 = 0;
    bool have = (i + 4 <= end);
    if (have) {
        a0 = __ldg(csr + i + 0);
        a1 = __ldg(csr + i + 1);
        a2 = __ldg(csr + i + 2);
        a3 = __ldg(csr + i + 3);
    }
    for (; i + 8 <= end; i += 4) {
        int b0 = __ldg(csr + i + 4);
        int b1 = __ldg(csr + i + 5);
        int b2 = __ldg(csr + i + 6);
        int b3 = __ldg(csr + i + 7);
        float v0 = __ldg(y + (size_t)a0 * W + lane);
        float v1 = __ldg(y + (size_t)a1 * W + lane);
        float v2 = __ldg(y + (size_t)a2 * W + lane);
        float v3 = __ldg(y + (size_t)a3 * W + lane);
        acc += (v0 + v1) + (v2 + v3);
        a0 = b0; a1 = b1; a2 = b2; a3 = b3;
    }
    if (have) {
        float v0 = __ldg(y + (size_t)a0 * W + lane);
        float v1 = __ldg(y + (size_t)a1 * W + lane);
        float v2 = __ldg(y + (size_t)a2 * W + lane);
        float v3 = __ldg(y + (size_t)a3 * W + lane);
        acc += (v0 + v1) + (v2 + v3);
        i += 4;
    }
    for (; i < end; i++)
        acc += __ldg(y + (size_t)__ldg(csr + i) * W + lane);
    float deg = (float)(end - beg);
    return acc / fmaxf(deg, 1.0f);
}

// ---------------------------------------------------------------------------
// Fused aggregate + ELU + NEXT-layer transform (shfl broadcast of h-row).
// ---------------------------------------------------------------------------
template <int OUT_NEXT>
__global__ void __launch_bounds__(256) agg_xform_kernel(
    const int* __restrict__ off, const int* __restrict__ csr,
    const float* __restrict__ y, const float* __restrict__ z,
    const float* __restrict__ Wl, const float* __restrict__ Wr,
    const float* __restrict__ bias,
    float* __restrict__ yn, float* __restrict__ zn)
{
    __shared__ float sWl[16 * OUT_NEXT];   // [k][o]
    __shared__ float sWr[16 * OUT_NEXT];
    __shared__ float sb[OUT_NEXT];
    for (int i = threadIdx.x; i < 16 * OUT_NEXT; i += 256) {
        int o = i / 16, k = i - o * 16;
        sWl[k * OUT_NEXT + o] = Wl[i];
        sWr[k * OUT_NEXT + o] = Wr[i];
    }
    if (threadIdx.x < OUT_NEXT) sb[threadIdx.x] = bias[threadIdx.x];
    __syncthreads();

    int lane = threadIdx.x & 15;
    int node = (blockIdx.x * 256 + threadIdx.x) >> 4;   // grid exact

    int beg = __ldg(off + node);
    int end = __ldg(off + node + 1);

    float mean = gather_mean<16>(csr, y, beg, end, lane);
    float v = elu_f(mean + __ldg(z + (size_t)node * 16 + lane));

    float accY = 0.0f;
    float accZ = (lane < OUT_NEXT) ? sb[lane] : 0.0f;
#pragma unroll
    for (int k = 0; k < 16; k++) {
        float hk = __shfl_sync(0xffffffffu, v, k, 16);
        if (lane < OUT_NEXT) {
            accY = fmaf(hk, sWl[k * OUT_NEXT + lane], accY);
            accZ = fmaf(hk, sWr[k * OUT_NEXT + lane], accZ);
        }
    }
    if (lane < OUT_NEXT) {
        yn[(size_t)node * OUT_NEXT + lane] = accY;
        zn[(size_t)node * OUT_NEXT + lane] = accZ;
    }
}

// ---------------------------------------------------------------------------
// Final aggregate (width 8) + ELU + log_softmax.
// ---------------------------------------------------------------------------
__global__ void __launch_bounds__(256) agg_final_kernel(
    const int* __restrict__ off, const int* __restrict__ csr,
    const float* __restrict__ y, const float* __restrict__ z,
    float* __restrict__ out)
{
    int lane = threadIdx.x & 7;
    int node = (blockIdx.x * 256 + threadIdx.x) >> 3;   // grid exact

    int beg = __ldg(off + node);
    int end = __ldg(off + node + 1);

    float mean = gather_mean<8>(csr, y, beg, end, lane);
    float v = elu_f(mean + __ldg(z + (size_t)node * 8 + lane));

    float m = v;
#pragma unroll
    for (int o = 4; o >= 1; o >>= 1)
        m = fmaxf(m, __shfl_xor_sync(0xffffffff, m, o, 8));
    float ex = expf(v - m);
    float s = ex;
#pragma unroll
    for (int o = 4; o >= 1; o >>= 1)
        s += __shfl_xor_sync(0xffffffff, s, o, 8);
    v = v - m - logf(s);

    out[(size_t)node * 8 + lane] = v;
}

// ---------------------------------------------------------------------------
extern "C" void kernel_launch(void* const* d_in, const int* in_sizes, int n_in,
                              void* d_out, int out_size)
{
    (void)in_sizes; (void)n_in; (void)out_size;

    const float* x   = (const float*)d_in[0];
    const int*   ei  = (const int*)d_in[1];   // int32 (JAX x64-disabled)
    const float* W1l = (const float*)d_in[2];
    const float* W1r = (const float*)d_in[3];
    const float* b1  = (const float*)d_in[4];
    const float* W2l = (const float*)d_in[5];
    const float* W2r = (const float*)d_in[6];
    const float* b2  = (const float*)d_in[7];
    const float* W3l = (const float*)d_in[8];
    const float* W3r = (const float*)d_in[9];
    const float* b3  = (const float*)d_in[10];
    float* out = (float*)d_out;

    const int* src = ei;
    const int* dst = ei + NE;

    float *pyA, *pzA, *pyB, *pzB;
    int *pcnt, *poff, *pcur, *pcsr;
    unsigned long long* pstate;
    cudaGetSymbolAddress((void**)&pyA,   g_yA);
    cudaGetSymbolAddress((void**)&pzA,   g_zA);
    cudaGetSymbolAddress((void**)&pyB,   g_yB);
    cudaGetSymbolAddress((void**)&pzB,   g_zB);
    cudaGetSymbolAddress((void**)&pcnt,  g_cnt);
    cudaGetSymbolAddress((void**)&poff,  g_off);
    cudaGetSymbolAddress((void**)&pcur,  g_cur);
    cudaGetSymbolAddress((void**)&pcsr,  g_csr);
    cudaGetSymbolAddress((void**)&pstate, g_state);

    const int nbN = (NN + 255) / 256;
    const int nbE = (NE + 255) / 256;

    // Fork: transform1 (independent of CSR build) runs on a side stream.
    // Created per call, never destroyed (kernel_launch runs only for the
    // correctness call + the single capture call; destroying a capturing
    // stream would invalidate capture).
    cudaStream_t s2;
    cudaStreamCreateWithFlags(&s2, cudaStreamNonBlocking);
    cudaEvent_t evFork, evJoin;
    cudaEventCreateWithFlags(&evFork, cudaEventDisableTiming);
    cudaEventCreateWithFlags(&evJoin, cudaEventDisableTiming);

    cudaEventRecord(evFork, 0);
    cudaStreamWaitEvent(s2, evFork, 0);
    transform2_kernel<48, 16><<<dim3(nbN, 2), 256, 0, s2>>>(x, W1l, W1r, b1, pyA, pzA);
    cudaEventRecord(evJoin, s2);

    // ---- CSR build on the main stream ----
    cudaMemsetAsync(pcnt, 0, NN * sizeof(int));
    cudaMemsetAsync(pstate, 0, NCHUNK * sizeof(unsigned long long));
    hist_kernel<<<nbE, 256>>>(dst, pcnt);
    scan_onepass_kernel<<<NCHUNK, 256>>>(pcnt, poff, pcur);
    place_kernel<<<nbE, 256>>>(src, dst, pcur, pcsr);

    cudaStreamWaitEvent(0, evJoin, 0);   // join transform1

    // ---- Layer 1 agg + layer 2 transform: -> yB,zB (16) ----
    agg_xform_kernel<16><<<NN * 16 / 256, 256>>>(poff, pcsr, pyA, pzA,
                                                 W2l, W2r, b2, pyB, pzB);
    // ---- Layer 2 agg + layer 3 transform: -> yA,zA (8) ----
    agg_xform_kernel<8><<<NN * 16 / 256, 256>>>(poff, pcsr, pyB, pzB,
                                                W3l, W3r, b3, pyA, pzA);
    // ---- Layer 3 agg + log_softmax ----
    agg_final_kernel<<<NN * 8 / 256, 256>>>(poff, pcsr, pyA, pzA, out);
}